// round 17
// baseline (speedup 1.0000x reference)
#include <cuda_runtime.h>
#include <cuda_fp16.h>
#include <cstdint>
#include <math.h>

// Problem constants
#define BATCH 4
#define SEQ   4096
#define DIM   1024
#define MROWS (BATCH * SEQ)          // 16384
#define NKVR  (3 * DIM)              // 3072 fused output channels

// Scan chunking
#define CHUNK_L 64
#define NCHUNK  (SEQ / CHUNK_L)      // 64

// GEMM tiling
#define BM 128
#define BN 128
#define BK 32                         // fp16 K elems per stage (64B rows)
#define KCHUNKS (DIM / BK)            // 32
#define NSTAGE 3
#define GTHREADS 256
#define GPERS 296                     // persistent grid: 2 CTAs/SM * 148 SMs

#define TILE_B  (128 * BK * 2)        // 8192 B per fp16 tile
#define STAGE_B (2 * TILE_B)          // A, B tiles = 16384 B
#define SMEM_TOTAL (NSTAGE * STAGE_B) // 49152 B

// ---------------------------------------------------------------------------
// Scratch (no cudaMalloc allowed)
// ---------------------------------------------------------------------------
__device__ __half g_kvh[MROWS * DIM];            // kv = k*v products (fp16)
__device__ __half g_rh[MROWS * DIM];             // r pre-sigmoid (fp16)
__device__ float g_chunk_sum[BATCH * NCHUNK * DIM];
__device__ float g_state_in[BATCH * NCHUNK * DIM];

__device__ __half g_xhi[MROWS * DIM];
__device__ __half g_wh[4 * DIM * DIM];           // [WkWv interleaved | Wr | Wo]
__device__ __half g_ohi[MROWS * DIM];            // wo_in fp16

// ---------------------------------------------------------------------------
// Helpers
// ---------------------------------------------------------------------------
__device__ __forceinline__ uint32_t smem_u32(const void* p) {
    uint32_t a;
    asm("{ .reg .u64 t; cvta.to.shared.u64 t, %1; cvt.u32.u64 %0, t; }"
        : "=r"(a) : "l"(p));
    return a;
}

__device__ __forceinline__ void cp_async16(uint32_t dst, const void* src) {
    asm volatile("cp.async.cg.shared.global [%0], [%1], 16;"
                 :: "r"(dst), "l"(src) : "memory");
}
__device__ __forceinline__ void cp_commit() {
    asm volatile("cp.async.commit_group;" ::: "memory");
}
__device__ __forceinline__ void cp_wait1() {
    asm volatile("cp.async.wait_group 1;" ::: "memory");
}

__device__ __forceinline__ void ldmx4(uint32_t* r, uint32_t addr) {
    asm volatile("ldmatrix.sync.aligned.m8n8.x4.shared.b16 {%0,%1,%2,%3}, [%4];"
                 : "=r"(r[0]), "=r"(r[1]), "=r"(r[2]), "=r"(r[3]) : "r"(addr));
}

__device__ __forceinline__ void mma_f16(float* d, const uint32_t* a,
                                        const uint32_t* b) {
    asm volatile(
        "mma.sync.aligned.m16n8k16.row.col.f32.f16.f16.f32 "
        "{%0,%1,%2,%3}, {%4,%5,%6,%7}, {%8,%9}, {%0,%1,%2,%3};"
        : "+f"(d[0]), "+f"(d[1]), "+f"(d[2]), "+f"(d[3])
        : "r"(a[0]), "r"(a[1]), "r"(a[2]), "r"(a[3]), "r"(b[0]), "r"(b[1]));
}

// SMEM swizzle for 64B rows (conflict-free ldmatrix)
__device__ __forceinline__ uint32_t sw_off(uint32_t r, uint32_t kb) {
    return r * 64 + (kb ^ (((r >> 1) & 3) << 4));
}

// ---------------------------------------------------------------------------
// Merged convert: y=0 -> x (grid-stride), y=1..4 -> weights with row remap:
// Wk row d -> 2d, Wv row d -> 2d+1, Wr -> 2048+d, Wo -> 3072+d.
// ---------------------------------------------------------------------------
__global__ void convert_all(const float* __restrict__ x,
                            const float* __restrict__ w0,
                            const float* __restrict__ w1,
                            const float* __restrict__ w2,
                            const float* __restrict__ w3,
                            __half* __restrict__ xdst,
                            __half* __restrict__ wdst)
{
    const int m = blockIdx.y;
    if (m == 0) {
        const int n4 = MROWS * DIM / 4;
        for (int i = blockIdx.x * blockDim.x + threadIdx.x; i < n4;
             i += gridDim.x * blockDim.x) {
            float4 f = ((const float4*)x)[i];
            __half2 p0 = __floats2half2_rn(f.x, f.y);
            __half2 p1 = __floats2half2_rn(f.z, f.w);
            ((uint2*)xdst)[i] = make_uint2(*(uint32_t*)&p0, *(uint32_t*)&p1);
        }
    } else {
        const int n4 = DIM * DIM / 4;
        const int ROW4 = DIM / 4;
        const float* src = (m == 1) ? w0 : (m == 2) ? w1 : (m == 3) ? w2 : w3;
        for (int i = blockIdx.x * blockDim.x + threadIdx.x; i < n4;
             i += gridDim.x * blockDim.x) {
            const int srow = i / ROW4;
            const int c4 = i - srow * ROW4;
            int drow;
            if (m == 1)      drow = 2 * srow;
            else if (m == 2) drow = 2 * srow + 1;
            else if (m == 3) drow = 2048 + srow;
            else             drow = 3072 + srow;
            float4 f = ((const float4*)src)[i];
            __half2 p0 = __floats2half2_rn(f.x, f.y);
            __half2 p1 = __floats2half2_rn(f.z, f.w);
            ((uint2*)wdst)[(size_t)drow * ROW4 + c4] =
                make_uint2(*(uint32_t*)&p0, *(uint32_t*)&p1);
        }
    }
}

// ---------------------------------------------------------------------------
// Persistent fp16 NT GEMM via mma.sync. Each CTA loops over output tiles
// (bm-major within bn for L2 weight reuse); next tile's first two pipeline
// stages are prefetched before the current epilogue to hide the bubble.
// MODE 0: fp32 C output. MODE 1: fused kvr epilogue (kv product + r).
// ---------------------------------------------------------------------------
template <int MODE>
__global__ __launch_bounds__(GTHREADS, 2)
void gemm_fp16(const __half* __restrict__ Ah,
               const __half* __restrict__ Bh,
               float* __restrict__ C, int ntiles)
{
    extern __shared__ char smem[];
    const uint32_t sb = smem_u32(smem);
    const int tid = threadIdx.x;
    const int wid = tid >> 5;
    const int lane = tid & 31;

    const int warp_m = (wid >> 1) * 32;   // 0,32,64,96
    const int warp_n = (wid & 1) * 64;    // 0,64

    auto issue_stage = [&](int bm, int bn, int c, int s) {
        const uint32_t stage = sb + s * STAGE_B;
#pragma unroll
        for (int tile = 0; tile < 2; tile++) {
            const __half* src = tile ? Bh : Ah;
            const int rowbase = tile ? bn : bm;
#pragma unroll
            for (int i = 0; i < 2; i++) {
                const int idx = i * 256 + tid;   // 0..511
                const uint32_t r = idx >> 2;
                const uint32_t kq = (idx & 3) * 16;
                const uint32_t dst = stage + tile * TILE_B + sw_off(r, kq);
                const char* sp = (const char*)(src + (size_t)(rowbase + r) * DIM
                                               + c * BK) + kq;
                cp_async16(dst, sp);
            }
        }
    };

    const int gA = lane >> 3, rlA = lane & 7;
    const int a_row_off = (gA & 1) * 8 + rlA;
    const int a_kb_off = (gA >> 1) * 16;
    const int b_row_off = (gA >> 1) * 8 + rlA;
    const int b_kb_off = (gA & 1) * 16;

    int tile0 = blockIdx.x;
    if (tile0 >= ntiles) return;

    // Prologue for first tile
    {
        const int bm = (tile0 & 127) * BM;
        const int bn = (tile0 >> 7) * BN;
        issue_stage(bm, bn, 0, 0); cp_commit();
        issue_stage(bm, bn, 1, 1); cp_commit();
    }

    for (int tile = tile0; tile < ntiles; tile += gridDim.x) {
        const int bm = (tile & 127) * BM;
        const int bn = (tile >> 7) * BN;

        float acc[2][8][4];
#pragma unroll
        for (int mt = 0; mt < 2; mt++)
#pragma unroll
            for (int nt = 0; nt < 8; nt++)
#pragma unroll
                for (int j = 0; j < 4; j++) acc[mt][nt][j] = 0.0f;

        for (int c = 0; c < KCHUNKS; c++) {
            cp_wait1();
            __syncthreads();
            if (c + 2 < KCHUNKS) issue_stage(bm, bn, c + 2, (c + 2) % NSTAGE);
            cp_commit();

            const uint32_t stage = sb + (c % NSTAGE) * STAGE_B;
            const uint32_t sB = stage + TILE_B;

#pragma unroll
            for (int ks = 0; ks < 2; ks++) {
                const uint32_t kbase = ks * 32;
                uint32_t a[2][4];
#pragma unroll
                for (int mt = 0; mt < 2; mt++) {
                    const uint32_t r = warp_m + mt * 16 + a_row_off;
                    const uint32_t kb = kbase + a_kb_off;
                    ldmx4(a[mt], stage + sw_off(r, kb));
                }
                uint32_t bh[8][2];
#pragma unroll
                for (int p = 0; p < 4; p++) {
                    const uint32_t n = warp_n + p * 16 + b_row_off;
                    const uint32_t kb = kbase + b_kb_off;
                    uint32_t t4[4];
                    ldmx4(t4, sB + sw_off(n, kb));
                    bh[2 * p][0] = t4[0]; bh[2 * p][1] = t4[1];
                    bh[2 * p + 1][0] = t4[2]; bh[2 * p + 1][1] = t4[3];
                }
#pragma unroll
                for (int mt = 0; mt < 2; mt++)
#pragma unroll
                    for (int nt = 0; nt < 8; nt++)
                        mma_f16(acc[mt][nt], a[mt], bh[nt]);
            }
            __syncthreads();
        }

        // Prefetch next tile's first two stages before the epilogue
        const int ntile = tile + gridDim.x;
        if (ntile < ntiles) {
            const int nbm = (ntile & 127) * BM;
            const int nbn = (ntile >> 7) * BN;
            issue_stage(nbm, nbn, 0, 0); cp_commit();
            issue_stage(nbm, nbn, 1, 1); cp_commit();
        }

        // Epilogue
        const int er = lane >> 2;
        const int ec = (lane & 3) * 2;
        if (MODE == 0) {
#pragma unroll
            for (int mt = 0; mt < 2; mt++) {
                const int row0 = bm + warp_m + mt * 16 + er;
#pragma unroll
                for (int nt = 0; nt < 8; nt++) {
                    const int col = bn + warp_n + nt * 8 + ec;
                    *(float2*)(C + (size_t)row0 * DIM + col) =
                        make_float2(acc[mt][nt][0], acc[mt][nt][1]);
                    *(float2*)(C + (size_t)(row0 + 8) * DIM + col) =
                        make_float2(acc[mt][nt][2], acc[mt][nt][3]);
                }
            }
        } else {
            if (bn < 2048) {
#pragma unroll
                for (int mt = 0; mt < 2; mt++) {
                    const int row0 = bm + warp_m + mt * 16 + er;
#pragma unroll
                    for (int nt = 0; nt < 8; nt++) {
                        const int col = bn + warp_n + nt * 8 + ec;
                        const int d = col >> 1;
                        g_kvh[(size_t)row0 * DIM + d] =
                            __float2half_rn(acc[mt][nt][0] * acc[mt][nt][1]);
                        g_kvh[(size_t)(row0 + 8) * DIM + d] =
                            __float2half_rn(acc[mt][nt][2] * acc[mt][nt][3]);
                    }
                }
            } else {
#pragma unroll
                for (int mt = 0; mt < 2; mt++) {
                    const int row0 = bm + warp_m + mt * 16 + er;
#pragma unroll
                    for (int nt = 0; nt < 8; nt++) {
                        const int col = bn - 2048 + warp_n + nt * 8 + ec;
                        *(__half2*)(g_rh + (size_t)row0 * DIM + col) =
                            __floats2half2_rn(acc[mt][nt][0], acc[mt][nt][1]);
                        *(__half2*)(g_rh + (size_t)(row0 + 8) * DIM + col) =
                            __floats2half2_rn(acc[mt][nt][2], acc[mt][nt][3]);
                    }
                }
            }
        }
    }
}

// ---------------------------------------------------------------------------
// Scan pass A: 2 channels/thread (half2 kv), per-chunk local reduction.
// ---------------------------------------------------------------------------
__global__ void scan_passA(const float* __restrict__ td)
{
    const int d0 = 2 * threadIdx.x;
    const int c = blockIdx.x;
    const int b = blockIdx.y;

    const float dec0 = expf(-expf(td[d0]));
    const float dec1 = expf(-expf(td[d0 + 1]));

    const size_t base = ((size_t)b * SEQ + (size_t)c * CHUNK_L) * DIM + d0;
    float s0 = 0.0f, s1 = 0.0f;
#pragma unroll 4
    for (int t = 0; t < CHUNK_L; t++) {
        float2 kv = __half22float2(*(const __half2*)(g_kvh + base + (size_t)t * DIM));
        s0 = fmaf(dec0, s0, kv.x);
        s1 = fmaf(dec1, s1, kv.y);
    }
    *(float2*)(g_chunk_sum + ((size_t)b * NCHUNK + c) * DIM + d0) =
        make_float2(s0, s1);
}

// ---------------------------------------------------------------------------
// Scan pass B: sequential carry across chunks.
// ---------------------------------------------------------------------------
__global__ void scan_passB(const float* __restrict__ td)
{
    const int d0 = 2 * threadIdx.x;
    const int b = blockIdx.x;

    const float dL0 = expf(-(float)CHUNK_L * expf(td[d0]));
    const float dL1 = expf(-(float)CHUNK_L * expf(td[d0 + 1]));

    float c0 = 0.0f, c1 = 0.0f;
#pragma unroll
    for (int c = 0; c < NCHUNK; c++) {
        const size_t idx = ((size_t)b * NCHUNK + c) * DIM + d0;
        *(float2*)(g_state_in + idx) = make_float2(c0, c1);
        float2 s = *(const float2*)(g_chunk_sum + idx);
        c0 = fmaf(dL0, c0, s.x);
        c1 = fmaf(dL1, c1, s.y);
    }
}

// ---------------------------------------------------------------------------
// Scan pass C: replay with incoming state; writes fp16 sigmoid(r)*wkv.
// ---------------------------------------------------------------------------
__global__ void scan_passC(const float* __restrict__ td,
                           const float* __restrict__ tf)
{
    const int d0 = 2 * threadIdx.x;
    const int c = blockIdx.x;
    const int b = blockIdx.y;

    const float dec0 = expf(-expf(td[d0]));
    const float dec1 = expf(-expf(td[d0 + 1]));
    const float eu0  = expf(tf[d0]);
    const float eu1  = expf(tf[d0 + 1]);

    float2 st = *(const float2*)(g_state_in + ((size_t)b * NCHUNK + c) * DIM + d0);

    const size_t rowbase = (size_t)b * SEQ + (size_t)c * CHUNK_L;
#pragma unroll 4
    for (int t = 0; t < CHUNK_L; t++) {
        const size_t off = (rowbase + t) * DIM + d0;
        float2 kv = __half22float2(*(const __half2*)(g_kvh + off));
        float2 r2 = __half22float2(*(const __half2*)(g_rh + off));
        float wkv0 = fmaf(eu0, kv.x, st.x);
        float wkv1 = fmaf(eu1, kv.y, st.y);
        st.x = fmaf(dec0, st.x, kv.x);
        st.y = fmaf(dec1, st.y, kv.y);
        float rs0 = 1.0f / (1.0f + expf(-r2.x));
        float rs1 = 1.0f / (1.0f + expf(-r2.y));
        *(__half2*)(g_ohi + off) = __floats2half2_rn(rs0 * wkv0, rs1 * wkv1);
    }
}

// ---------------------------------------------------------------------------
// Launch
// ---------------------------------------------------------------------------
extern "C" void kernel_launch(void* const* d_in, const int* in_sizes, int n_in,
                              void* d_out, int out_size)
{
    const float* x  = (const float*)d_in[0];
    const float* Wk = (const float*)d_in[1];
    const float* Wv = (const float*)d_in[2];
    const float* Wr = (const float*)d_in[3];
    const float* Wo = (const float*)d_in[4];
    const float* td = (const float*)d_in[5];
    const float* tf = (const float*)d_in[6];
    float* out = (float*)d_out;

    __half *xhi, *wh, *ohi;
    cudaGetSymbolAddress((void**)&xhi, g_xhi);
    cudaGetSymbolAddress((void**)&wh,  g_wh);
    cudaGetSymbolAddress((void**)&ohi, g_ohi);

    cudaFuncSetAttribute(gemm_fp16<0>,
                         cudaFuncAttributeMaxDynamicSharedMemorySize, SMEM_TOTAL);
    cudaFuncSetAttribute(gemm_fp16<1>,
                         cudaFuncAttributeMaxDynamicSharedMemorySize, SMEM_TOTAL);

    // Single merged convert launch
    convert_all<<<dim3(512, 5), 256>>>(x, Wk, Wv, Wr, Wo, xhi, wh);

    // Fused k|v|r projection: persistent, kv-product epilogue
    gemm_fp16<1><<<GPERS, GTHREADS, SMEM_TOTAL>>>(xhi, wh, nullptr,
                                                  (NKVR / BN) * (MROWS / BM));

    // Chunked linear scan
    dim3 sgrid(NCHUNK, BATCH);
    scan_passA<<<sgrid, DIM / 2>>>(td);
    scan_passB<<<BATCH, DIM / 2>>>(td);
    scan_passC<<<sgrid, DIM / 2>>>(td, tf);

    // Output projection: persistent, fp32 output
    gemm_fp16<0><<<GPERS, GTHREADS, SMEM_TOTAL>>>(ohi,
        wh + 3 * (size_t)DIM * DIM, out, (DIM / BN) * (MROWS / BM));
}